// round 15
// baseline (speedup 1.0000x reference)
#include <cuda_runtime.h>
#include <cuda_fp16.h>
#include <cstdint>

#define BH_  64
#define LQ_  1024
#define LK_  1024
#define DD_  64
#define TQ_  32
#define NT   256
#define PSTR_H 2064          // S/P row bytes (1032 fp16; 129×16B -> conflict-free ldmatrix)
#define KROWB  144           // K/V smem row bytes (72 fp16)
#define KTILE  128           // K/V tile rows (single plane)
#define OFF_KV (TQ_*PSTR_H)            // 66048
#define KBUFSZ (KTILE*KROWB)           // 18432
#define OFF_Q  (OFF_KV + 2*KBUFSZ)     // 102912
#define QPLANE (TQ_*KROWB)             // 4608
#define SM_TOTAL (OFF_Q + QPLANE)      // 107520 -> 2 CTAs/SM

__device__ __half g_QH[BH_*LQ_*DD_];
__device__ __half g_KH[BH_*LK_*DD_];
__device__ __half g_VH[BH_*LK_*DD_];

__device__ __forceinline__ uint32_t s2u(const void* p) {
    uint32_t a;
    asm("{.reg .u64 t; cvta.to.shared.u64 t, %1; cvt.u32.u64 %0, t;}" : "=r"(a) : "l"(p));
    return a;
}
__device__ __forceinline__ void lm4(uint32_t* r, uint32_t addr) {
    asm volatile("ldmatrix.sync.aligned.m8n8.x4.shared.b16 {%0,%1,%2,%3}, [%4];"
                 : "=r"(r[0]), "=r"(r[1]), "=r"(r[2]), "=r"(r[3]) : "r"(addr));
}
__device__ __forceinline__ void lm4t(uint32_t* r, uint32_t addr) {
    asm volatile("ldmatrix.sync.aligned.m8n8.x4.trans.shared.b16 {%0,%1,%2,%3}, [%4];"
                 : "=r"(r[0]), "=r"(r[1]), "=r"(r[2]), "=r"(r[3]) : "r"(addr));
}
__device__ __forceinline__ void mma16816(float* c, const uint32_t* a, uint32_t b0, uint32_t b1) {
    asm volatile("mma.sync.aligned.m16n8k16.row.col.f32.f16.f16.f32 "
                 "{%0,%1,%2,%3}, {%4,%5,%6,%7}, {%8,%9}, {%0,%1,%2,%3};"
                 : "+f"(c[0]), "+f"(c[1]), "+f"(c[2]), "+f"(c[3])
                 : "r"(a[0]), "r"(a[1]), "r"(a[2]), "r"(a[3]), "r"(b0), "r"(b1));
}
__device__ __forceinline__ void cp16(char* dst, const void* src) {
    uint32_t s = s2u(dst);
    asm volatile("cp.async.cg.shared.global [%0], [%1], 16;" :: "r"(s), "l"(src));
}
__device__ __forceinline__ void cp_commit() { asm volatile("cp.async.commit_group;"); }
__device__ __forceinline__ void cp_wait0() { asm volatile("cp.async.wait_group 0;"); }
__device__ __forceinline__ void cp_wait1() { asm volatile("cp.async.wait_group 1;"); }

__device__ __forceinline__ uint32_t pack_hi2(float a, float b) {
    __half2 h = __floats2half2_rn(a, b);
    return *(uint32_t*)&h;
}

// ---------------- kernel 1: fp32 -> fp16 (single plane each) ----------------
__global__ void __launch_bounds__(256) cvt_kernel(const float* __restrict__ Q,
                                                  const float* __restrict__ K,
                                                  const float* __restrict__ V)
{
    const int which = blockIdx.y;
    const float* src = (which == 0) ? Q : (which == 1) ? K : V;
    __half* dh = (which == 0) ? g_QH : (which == 1) ? g_KH : g_VH;
    const float sc = (which == 0) ? 0.125f : 1.0f;

    size_t i = ((size_t)blockIdx.x * 256 + threadIdx.x) * 4;
    float4 f = *(const float4*)(src + i);
    f.x *= sc; f.y *= sc; f.z *= sc; f.w *= sc;
    uint2 h;
    h.x = pack_hi2(f.x, f.y); h.y = pack_hi2(f.z, f.w);
    *(uint2*)(dh + i) = h;
}

// load one 128-row fp16 tile (single plane)
__device__ __forceinline__ void pf_t128(const __half* __restrict__ gh, char* buf, int tid) {
    #pragma unroll
    for (int it = 0; it < 4; ++it) {
        int idx = tid + it * NT;          // 0..1023
        int r = idx >> 3, c = idx & 7;
        cp16(buf + r * KROWB + c * 16, (const char*)(gh + r * DD_) + c * 16);
    }
}

// ---------------- kernel 2: fused attention (2 CTAs/SM, TQ=32) ----------------
__global__ void __launch_bounds__(NT, 2)
attn_kernel(const int* __restrict__ Mg, const float* __restrict__ QMg,
            float* __restrict__ out_o, float* __restrict__ out_a)
{
    extern __shared__ char smem[];
    char* kvb   = smem + OFF_KV;
    char* qbase = smem + OFF_Q;

    const int tid  = threadIdx.x;
    const int lane = tid & 31;
    const int wid  = tid >> 5;            // 0..7
    const int bh   = blockIdx.y;
    const int q0   = blockIdx.x * TQ_;

    const size_t qoff = ((size_t)bh * LQ_ + q0) * DD_;
    const size_t koff = (size_t)bh * LK_ * DD_;

    // ---- prefetch Q (1 chunk/thread) + K tiles 0/1 ----
    {
        int r = tid >> 3, c = tid & 7;
        cp16(qbase + r * KROWB + c * 16, (const char*)(g_QH + qoff + r * DD_) + c * 16);
    }
    pf_t128(g_KH + koff, kvb, tid);
    cp_commit();
    pf_t128(g_KH + koff + KTILE * DD_, kvb + KBUFSZ, tid);
    cp_commit();

    // ================ phase 2: S = (Q/8)K^T -> Pbuf fp16 (8 tiles of 128 k) ================
    const int qh2 = wid >> 2, kg = wid & 3;
    const int q0w = qh2 * 16, kb0 = kg * 16;

    uint32_t aH[4][4];

    #pragma unroll 1
    for (int t = 0; t < 8; ++t) {
        cp_wait1();
        __syncthreads();

        if (t == 0) {
            const uint32_t uH = s2u(qbase);
            const int arow = q0w + (lane & 15);
            #pragma unroll
            for (int ds = 0; ds < 4; ++ds) {
                const int acol = ds * 16 + ((lane >> 4) & 1) * 8;
                lm4(aH[ds], uH + arow * KROWB + acol * 2);
            }
        }

        const uint32_t sH = s2u(kvb + (t & 1) * KBUFSZ);
        const int srow = q0w + (lane >> 2);
        char* r0 = smem + srow * PSTR_H;
        char* r1 = smem + (srow + 8) * PSTR_H;

        #pragma unroll
        for (int h = 0; h < 2; ++h) {
            float accA[2][4];
            #pragma unroll
            for (int j = 0; j < 2; ++j)
                #pragma unroll
                for (int e = 0; e < 4; ++e) accA[j][e] = 0.f;

            const int brow = h * 64 + kb0 + ((lane >> 4) & 1) * 8 + (lane & 7);
            #pragma unroll
            for (int ds = 0; ds < 4; ++ds) {
                const int bcol = ds * 16 + ((lane >> 3) & 1) * 8;
                uint32_t bH[4];
                lm4(bH, sH + brow * KROWB + bcol * 2);
                mma16816(accA[0], aH[ds], bH[0], bH[1]);
                mma16816(accA[1], aH[ds], bH[2], bH[3]);
            }

            #pragma unroll
            for (int j = 0; j < 2; ++j) {
                const int col = t * KTILE + h * 64 + kb0 + j * 8 + 2 * (lane & 3);
                *(uint32_t*)(r0 + col * 2) = pack_hi2(accA[j][0], accA[j][1]);
                *(uint32_t*)(r1 + col * 2) = pack_hi2(accA[j][2], accA[j][3]);
            }
        }

        __syncthreads();
        if (t + 2 < 8) {
            pf_t128(g_KH + koff + (size_t)(t + 2) * KTILE * DD_, kvb + (t & 1) * KBUFSZ, tid);
        } else {
            // V tiles 0/1 (128-row) -> same double buffers
            pf_t128(g_VH + koff + (size_t)(t - 6) * KTILE * DD_, kvb + (t & 1) * KBUFSZ, tid);
        }
        cp_commit();
    }

    // ================ phase 3: mask + softmax; p back as fp16 + out_a fp32 ================
    // mask loads software-pipelined one row ahead
    int4 mreg[8];
    {
        const int4* mrow = (const int4*)(Mg + ((size_t)bh * LQ_ + q0 + wid * 4) * LK_);
        #pragma unroll
        for (int c = 0; c < 4; ++c) {
            const int idx = c * 32 + lane;
            mreg[2*c]   = __ldcs(mrow + 2 * idx);
            mreg[2*c+1] = __ldcs(mrow + 2 * idx + 1);
        }
    }

    #pragma unroll 1
    for (int i = 0; i < 4; ++i) {
        const int q = wid * 4 + i;
        char* rowb = smem + q * PSTR_H;

        int4 mnext[8];
        if (i < 3) {
            const int4* mr2 = (const int4*)(Mg + ((size_t)bh * LQ_ + q0 + q + 1) * LK_);
            #pragma unroll
            for (int c = 0; c < 4; ++c) {
                const int idx = c * 32 + lane;
                mnext[2*c]   = __ldcs(mr2 + 2 * idx);
                mnext[2*c+1] = __ldcs(mr2 + 2 * idx + 1);
            }
        }

        float v[32];
        float mx = -3.0e38f;
        #pragma unroll
        for (int c = 0; c < 4; ++c) {
            const int idx = c * 32 + lane;
            uint4 sv = *(uint4*)(rowb + idx * 16);
            int4 ma = mreg[2*c], mb = mreg[2*c+1];
            float2 f0 = __half22float2(*(__half2*)&sv.x);
            float2 f1 = __half22float2(*(__half2*)&sv.y);
            float2 f2 = __half22float2(*(__half2*)&sv.z);
            float2 f3 = __half22float2(*(__half2*)&sv.w);
            float* vv = v + c * 8;
            vv[0] = (ma.x == 0) ? -1.0e9f : f0.x;
            vv[1] = (ma.y == 0) ? -1.0e9f : f0.y;
            vv[2] = (ma.z == 0) ? -1.0e9f : f1.x;
            vv[3] = (ma.w == 0) ? -1.0e9f : f1.y;
            vv[4] = (mb.x == 0) ? -1.0e9f : f2.x;
            vv[5] = (mb.y == 0) ? -1.0e9f : f2.y;
            vv[6] = (mb.z == 0) ? -1.0e9f : f3.x;
            vv[7] = (mb.w == 0) ? -1.0e9f : f3.y;
            #pragma unroll
            for (int e = 0; e < 8; ++e) mx = fmaxf(mx, vv[e]);
        }
        #pragma unroll
        for (int o = 16; o > 0; o >>= 1)
            mx = fmaxf(mx, __shfl_xor_sync(0xffffffffu, mx, o));

        float sum = 0.f;
        #pragma unroll
        for (int e = 0; e < 32; ++e) { v[e] = __expf(v[e] - mx); sum += v[e]; }
        #pragma unroll
        for (int o = 16; o > 0; o >>= 1)
            sum += __shfl_xor_sync(0xffffffffu, sum, o);

        const float sc = QMg[(size_t)bh * LQ_ + q0 + q] / sum;
        float* arow = out_a ? (out_a + ((size_t)bh * LQ_ + q0 + q) * LK_) : nullptr;
        #pragma unroll
        for (int c = 0; c < 4; ++c) {
            const int idx = c * 32 + lane;
            float* vv = v + c * 8;
            #pragma unroll
            for (int e = 0; e < 8; ++e) vv[e] *= sc;
            if (arow) {
                __stcs((float4*)(arow + idx * 8),     make_float4(vv[0], vv[1], vv[2], vv[3]));
                __stcs((float4*)(arow + idx * 8 + 4), make_float4(vv[4], vv[5], vv[6], vv[7]));
            }
            uint4 pk;
            pk.x = pack_hi2(vv[0], vv[1]); pk.y = pack_hi2(vv[2], vv[3]);
            pk.z = pack_hi2(vv[4], vv[5]); pk.w = pack_hi2(vv[6], vv[7]);
            *(uint4*)(rowb + idx * 16) = pk;
        }

        if (i < 3) {
            #pragma unroll
            for (int c2 = 0; c2 < 8; ++c2) mreg[c2] = mnext[c2];
        }
    }

    // ================ phase 4: O = P @ V — 8 tiles of 128 k, warp = (qh4, nh, kh) ==========
    const int qh4 = wid >> 2;            // 0..1
    const int nh  = (wid >> 1) & 1;      // 0..1
    const int kh  = wid & 1;             // 0..1 (64-k half within the 128-k tile)
    const int q0o = qh4 * 16, n0 = nh * 32;
    const uint32_t pbase = s2u(smem);

    float oa[4][4];
    #pragma unroll
    for (int j = 0; j < 4; ++j)
        #pragma unroll
        for (int e = 0; e < 4; ++e) oa[j][e] = 0.f;

    const int arow = q0o + (lane & 15);
    const int vrl  = ((lane >> 3) & 1) * 8 + (lane & 7);
    const int vsub = ((lane >> 4) & 1) * 8;

    #pragma unroll 1
    for (int t = 0; t < 8; ++t) {
        if (t == 7) cp_wait0(); else cp_wait1();
        __syncthreads();                 // t==0 also publishes phase-3 p planes

        const uint32_t vH = s2u(kvb + (t & 1) * KBUFSZ);

        #pragma unroll
        for (int ks = 0; ks < 4; ++ks) {
            const int k0 = kh * 64 + ks * 16;
            uint32_t a4[4];
            const uint32_t ab = pbase + arow * PSTR_H +
                                2 * (t * KTILE + k0 + ((lane >> 4) & 1) * 8);
            lm4(a4, ab);

            const uint32_t vrow = (uint32_t)(k0 + vrl) * KROWB;
            #pragma unroll
            for (int nb2 = 0; nb2 < 2; ++nb2) {
                uint32_t b4[4];
                lm4t(b4, vH + vrow + (uint32_t)(n0 + nb2 * 16 + vsub) * 2);
                mma16816(oa[nb2 * 2 + 0], a4, b4[0], b4[1]);
                mma16816(oa[nb2 * 2 + 1], a4, b4[2], b4[3]);
            }
        }

        __syncthreads();
        if (t + 2 < 8) {
            pf_t128(g_VH + koff + (size_t)(t + 2) * KTILE * DD_, kvb + (t & 1) * KBUFSZ, tid);
            cp_commit();
        }
    }

    // ---- kh reduction via scratch in dead V buffer kvb[0] ----
    float* scr = (float*)kvb;            // [4 grp][16][34] floats = 8704 B < 18432
    const int grp = qh4 * 2 + nh;
    __syncthreads();
    if (kh == 1) {
        #pragma unroll
        for (int j = 0; j < 4; ++j) {
            const int cl = j * 8 + 2 * (lane & 3);
            float* s0 = scr + grp * (16 * 34) + (lane >> 2) * 34 + cl;
            *(float2*)s0 = make_float2(oa[j][0], oa[j][1]);
            *(float2*)(s0 + 8 * 34) = make_float2(oa[j][2], oa[j][3]);
        }
    }
    __syncthreads();
    if (kh == 0 && out_o) {
        const int row0 = q0 + q0o + (lane >> 2);
        #pragma unroll
        for (int j = 0; j < 4; ++j) {
            const int cl = j * 8 + 2 * (lane & 3);
            float2 s0 = *(float2*)(scr + grp * (16 * 34) + (lane >> 2) * 34 + cl);
            float2 s1 = *(float2*)(scr + grp * (16 * 34) + ((lane >> 2) + 8) * 34 + cl);
            float* o0 = out_o + ((size_t)bh * LQ_ + row0) * DD_ + n0 + cl;
            *(float2*)o0 = make_float2(oa[j][0] + s0.x, oa[j][1] + s0.y);
            *(float2*)(o0 + 8 * DD_) = make_float2(oa[j][2] + s1.x, oa[j][3] + s1.y);
        }
    }
}

extern "C" void kernel_launch(void* const* d_in, const int* in_sizes, int n_in,
                              void* d_out, int out_size)
{
    const float* q  = (const float*)d_in[0];
    const float* k  = (const float*)d_in[1];
    const float* v  = (const float*)d_in[2];
    const int*   m  = (const int*)d_in[3];
    const float* qm = (const float*)d_in[4];

    const long long NO = (long long)BH_ * LQ_ * DD_;
    const long long NA = (long long)BH_ * LQ_ * LK_;

    float* out_o = nullptr;
    float* out_a = nullptr;
    if ((long long)out_size >= NO + NA) {
        out_o = (float*)d_out;
        out_a = (float*)d_out + NO;
    } else if ((long long)out_size == NA) {
        out_a = (float*)d_out;
    } else {
        out_o = (float*)d_out;
    }

    cvt_kernel<<<dim3((BH_*LQ_*DD_) / (256 * 4), 3), 256>>>(q, k, v);

    cudaFuncSetAttribute(attn_kernel,
                         cudaFuncAttributeMaxDynamicSharedMemorySize, SM_TOTAL);
    attn_kernel<<<dim3(LQ_ / TQ_, BH_), NT, SM_TOTAL>>>(m, qm, out_o, out_a);
}